// round 15
// baseline (speedup 1.0000x reference)
#include <cuda_runtime.h>
#include <cuda.h>
#include <cuda_fp16.h>
#include <math.h>
#include <stdint.h>

#define BB 64
#define SS 1024
#define EE 1024
#define DD 512

// ---------------- device scratch ----------------
__device__ float  g_hp[BB * DD];            // h_proj + bias  [B, D]
__device__ __half g_ench[(size_t)BB * SS * EE];  // enc in fp16 (134 MB)
__device__ __half g_WeTh[DD * EE];          // W_e^T in fp16 [D(n), E2(k)]
__device__ float  g_pscore[4 * BB * SS];    // per-n-tile score partials
__device__ float  g_ctx_part[16 * BB * EE]; // context partials (16 S-slices)

// ---------------- helpers ----------------
__device__ __forceinline__ uint32_t smem_u32(const void* p) {
    uint32_t a;
    asm("{ .reg .u64 t; cvta.to.shared.u64 t, %1; cvt.u32.u64 %0, t; }" : "=r"(a) : "l"(p));
    return a;
}

#define MBARRIER_INIT(addr, cnt) \
    asm volatile("mbarrier.init.shared.b64 [%0], %1;" :: "r"(addr), "r"(cnt) : "memory")
#define MBARRIER_INVAL(addr) \
    asm volatile("mbarrier.inval.shared.b64 [%0];" :: "r"(addr) : "memory")
#define MBARRIER_EXPECT_TX(addr, bytes) \
    asm volatile("mbarrier.arrive.expect_tx.shared.b64 _, [%0], %1;" :: "r"(addr), "r"(bytes) : "memory")
#define MBARRIER_WAIT_PARITY(addr, parity) do {                                     \
    uint32_t _m = (addr), _p = (parity);                                            \
    asm volatile(                                                                   \
        "{\n\t.reg .pred P1;\n\t"                                                   \
        "WL_%=:\n\t"                                                                \
        "mbarrier.try_wait.parity.acquire.cta.shared::cta.b64 P1, [%0], %1, 0x989680;\n\t" \
        "@P1 bra.uni WD_%=;\n\t"                                                    \
        "bra.uni WL_%=;\n\t"                                                        \
        "WD_%=:\n\t}"                                                               \
        :: "r"(_m), "r"(_p) : "memory");                                            \
} while (0)
#define TMA_LOAD_2D(smem, map, cx, cy, mbar)                                        \
    asm volatile(                                                                   \
        "cp.async.bulk.tensor.2d.shared::cta.global.tile.mbarrier::complete_tx::bytes " \
        "[%0], [%1, {%2, %3}], [%4];"                                               \
        :: "r"(smem), "l"(map), "r"(cx), "r"(cy), "r"(mbar) : "memory")

__device__ __forceinline__ uint32_t pack_half2(float lo, float hi) {
    uint32_t r;
    asm("cvt.rn.f16x2.f32 %0, %1, %2;" : "=r"(r) : "f"(hi), "f"(lo));
    return r;
}

__device__ __forceinline__ void mma_f16(float c[4], uint32_t a0, uint32_t a1,
                                        uint32_t a2, uint32_t a3, uint32_t b0,
                                        uint32_t b1) {
    asm volatile(
        "mma.sync.aligned.m16n8k16.row.col.f32.f16.f16.f32 "
        "{%0,%1,%2,%3}, {%4,%5,%6,%7}, {%8,%9}, {%0,%1,%2,%3};"
        : "+f"(c[0]), "+f"(c[1]), "+f"(c[2]), "+f"(c[3])
        : "r"(a0), "r"(a1), "r"(a2), "r"(a3), "r"(b0), "r"(b1));
}

// ---------------- tiling ----------------
#define BM 128
#define BN 128
#define BK 32
#define NCHUNK (EE / BK)        // 32
#define A_SZB (BM * 64)         // 8192 (64B rows, TMA SW64)
#define B_SZB (BN * 64)         // 8192
#define STAGE_B (A_SZB + B_SZB) // 16384
#define OFF_SLOT 1024
#define OFF_SHP (OFF_SLOT + 4 * STAGE_B)      // 66560
#define OFF_SV  (OFF_SHP + BN * 4)
#define OFF_RED OFF_SLOT                      // red[128][17] aliases slot 0 (dead)
#define SMEM_SIZE (OFF_SV + BN * 4)           // 67584 B -> 2 CTAs/SM

// ---------------------------------------------------------------------------
// fused prep: convert enc->fp16 (16 elems/thread, MLP 4) | transpose W_e |
// hproj. 256 thr.
// ---------------------------------------------------------------------------
#define CONV_BLOCKS ((BB * SS * EE) / (256 * 16))  // 8192
#define TRANS_BLOCKS ((EE / 32) * (DD / 32))       // 512
#define HPROJ_BLOCKS ((DD / 256) * BB)             // 128
#define PREP_BLOCKS (CONV_BLOCKS + TRANS_BLOCKS + HPROJ_BLOCKS)

__global__ void __launch_bounds__(256) prep_kernel(
    const float* __restrict__ enc, const float* __restrict__ attn_W,
    const float* __restrict__ attn_b, const float* __restrict__ hidden) {
    __shared__ float sbuf[32 * 33 > 512 ? 32 * 33 : 512];
    int bx = blockIdx.x;
    int tid = threadIdx.x;
    if (bx < CONV_BLOCKS) {
        size_t base = ((size_t)bx * 256 + tid) * 16;
        float4 v0 = __ldcs((const float4*)(enc + base));
        float4 v1 = __ldcs((const float4*)(enc + base + 4));
        float4 v2 = __ldcs((const float4*)(enc + base + 8));
        float4 v3 = __ldcs((const float4*)(enc + base + 12));
        uint4 o0, o1;
        o0.x = pack_half2(v0.x, v0.y);
        o0.y = pack_half2(v0.z, v0.w);
        o0.z = pack_half2(v1.x, v1.y);
        o0.w = pack_half2(v1.z, v1.w);
        o1.x = pack_half2(v2.x, v2.y);
        o1.y = pack_half2(v2.z, v2.w);
        o1.z = pack_half2(v3.x, v3.y);
        o1.w = pack_half2(v3.z, v3.w);
        __stcs((uint4*)(&g_ench[base]), o0);
        __stcs((uint4*)(&g_ench[base + 8]), o1);
    } else if (bx < CONV_BLOCKS + TRANS_BLOCKS) {
        int id = bx - CONV_BLOCKS;
        int k0 = (id & 31) * 32, d0 = (id >> 5) * 32;
        int x = tid & 31, y = tid >> 5;
        float (*t)[33] = (float(*)[33])sbuf;
        for (int i = y; i < 32; i += 8)
            t[i][x] = attn_W[(size_t)(DD + k0 + i) * DD + d0 + x];
        __syncthreads();
        for (int i = y; i < 32; i += 8)
            g_WeTh[(size_t)(d0 + i) * EE + k0 + x] = __float2half_rn(t[x][i]);
    } else {
        int id = bx - CONV_BLOCKS - TRANS_BLOCKS;
        int b = id >> 1;
        int d = (id & 1) * 256 + tid;
        for (int i = tid; i < DD; i += 256) sbuf[i] = hidden[b * DD + i];
        __syncthreads();
        float acc = attn_b[d];
#pragma unroll 8
        for (int k = 0; k < DD; k++) acc += sbuf[k] * attn_W[k * DD + d];
        g_hp[b * DD + d] = acc;
    }
}

// ---------------------------------------------------------------------------
// scores: fp16 m16n8k16 GEMM (128x128 tile, K=1024), TMA-fed 4-slot pipeline,
// 2 CTAs/SM (launch_bounds(256,2)) -> 4 warps/SMSP.  [unchanged — proven]
// ---------------------------------------------------------------------------
__global__ void __launch_bounds__(256, 2)
scores_mma_kernel(const __grid_constant__ CUtensorMap tmA,
                  const __grid_constant__ CUtensorMap tmB,
                  const float* __restrict__ vW) {
    extern __shared__ char smem[];
    uint32_t sb = smem_u32(smem);
    int tid = threadIdx.x;
    int wid = tid >> 5, lid = tid & 31;
    int gid = lid >> 2, tig = lid & 3;
    int wm = wid >> 2, wn = wid & 3;       // warp grid 2(m) x 4(n)
    int nt = blockIdx.x;                   // n tile (0..3)
    int r0 = blockIdx.y * BM;              // global row
    int b = r0 / SS;
    int n0 = nt * BN;
    int swt = (tig ^ ((gid >> 1) & 3)) * 16;   // loop-invariant swizzled 16B offset

    float* shp = (float*)(smem + OFF_SHP);
    float* sv  = (float*)(smem + OFF_SV);
    for (int i = tid; i < BN; i += 256) {
        shp[i] = g_hp[b * DD + n0 + i];
        sv[i]  = vW[n0 + i];
    }
    if (tid == 0) {
#pragma unroll
        for (int p = 0; p < 4; p++) MBARRIER_INIT(sb + 16 + p * 8, 1);
    }
    __syncthreads();

    if (tid == 0) {
#pragma unroll
        for (int p = 0; p < 4; p++) {
            uint32_t slot = sb + OFF_SLOT + p * STAGE_B;
            MBARRIER_EXPECT_TX(sb + 16 + p * 8, (uint32_t)STAGE_B);
            TMA_LOAD_2D(slot, &tmA, p * BK, r0, sb + 16 + p * 8);
            TMA_LOAD_2D(slot + A_SZB, &tmB, p * BK, n0, sb + 16 + p * 8);
        }
    }

    float acc[4][4][4];
#pragma unroll
    for (int mf = 0; mf < 4; mf++)
#pragma unroll
        for (int nf = 0; nf < 4; nf++)
#pragma unroll
            for (int q = 0; q < 4; q++) acc[mf][nf][q] = 0.f;

#pragma unroll 4
    for (int c = 0; c < NCHUNK; c++) {
        int slot = c & 3;
        uint32_t mb = sb + 16 + slot * 8;
        MBARRIER_WAIT_PARITY(mb, (uint32_t)((c >> 2) & 1));

        const char* fA = smem + OFF_SLOT + slot * STAGE_B;
        const char* fB = fA + A_SZB;

        uint4 alo[4], ahi[4], bv[4];   // 8 halves each: phys k = 8*tig..+7
#pragma unroll
        for (int mf = 0; mf < 4; mf++) {
            int m0 = wm * 64 + mf * 16 + gid;
            alo[mf] = *(const uint4*)(fA + m0 * 64 + swt);
            ahi[mf] = *(const uint4*)(fA + (m0 + 8) * 64 + swt);
        }
#pragma unroll
        for (int nf = 0; nf < 4; nf++) {
            int nr = wn * 32 + nf * 8 + gid;
            bv[nf] = *(const uint4*)(fB + nr * 64 + swt);
        }
        __syncthreads();   // all warps consumed this slot
        if (c + 4 < NCHUNK && tid == 0) {
            uint32_t sdst = sb + OFF_SLOT + slot * STAGE_B;
            MBARRIER_EXPECT_TX(mb, (uint32_t)STAGE_B);
            TMA_LOAD_2D(sdst, &tmA, (c + 4) * BK, r0, mb);
            TMA_LOAD_2D(sdst + A_SZB, &tmB, (c + 4) * BK, n0, mb);
        }

        // instr 0: half-pairs 0,1 (phys k 8t..8t+3)
#pragma unroll
        for (int mf = 0; mf < 4; mf++)
#pragma unroll
            for (int nf = 0; nf < 4; nf++)
                mma_f16(acc[mf][nf], alo[mf].x, ahi[mf].x, alo[mf].y, ahi[mf].y,
                        bv[nf].x, bv[nf].y);
        // instr 1: half-pairs 2,3 (phys k 8t+4..8t+7)
#pragma unroll
        for (int mf = 0; mf < 4; mf++)
#pragma unroll
            for (int nf = 0; nf < 4; nf++)
                mma_f16(acc[mf][nf], alo[mf].z, ahi[mf].z, alo[mf].w, ahi[mf].w,
                        bv[nf].z, bv[nf].w);
    }
    __syncthreads();   // slots dead; red aliases slot 0

    // ---- epilogue: score partial = sum_n v[n] * tanh(acc + hp[n]) ----
    float* red = (float*)(smem + OFF_RED);  // [128][17]
#pragma unroll
    for (int mf = 0; mf < 4; mf++) {
#pragma unroll
        for (int half = 0; half < 2; half++) {
            int r = wm * 64 + mf * 16 + half * 8 + gid;
            float s = 0.f;
#pragma unroll
            for (int nf = 0; nf < 4; nf++) {
                int nl = wn * 32 + nf * 8 + tig * 2;
                float e0 = acc[mf][nf][half * 2 + 0] + shp[nl];
                float e1 = acc[mf][nf][half * 2 + 1] + shp[nl + 1];
                float t0, t1;
                asm("tanh.approx.f32 %0, %1;" : "=f"(t0) : "f"(e0));
                asm("tanh.approx.f32 %0, %1;" : "=f"(t1) : "f"(e1));
                s = fmaf(sv[nl], t0, s);
                s = fmaf(sv[nl + 1], t1, s);
            }
            red[r * 17 + wn * 4 + tig] = s;
        }
    }
    __syncthreads();
    if (tid < BM) {
        float s = 0.f;
#pragma unroll
        for (int t = 0; t < 16; t++) s += red[tid * 17 + t];
        g_pscore[nt * (BB * SS) + r0 + tid] = s;
    }
    __syncthreads();
    if (tid == 0) {
#pragma unroll
        for (int p = 0; p < 4; p++) MBARRIER_INVAL(sb + 16 + p * 8);
    }
}

// ---------------------------------------------------------------------------
// softmax: combine 4 partials, mask, softmax over S. grid(64), 512 threads.
// ---------------------------------------------------------------------------
__global__ void softmax_kernel(const int* __restrict__ mask,
                               float* __restrict__ wout) {
    int b = blockIdx.x;
    __shared__ float sc[SS];
    __shared__ float redbuf[512];
    int tid = threadIdx.x;

    float lmax = -3.402823466e38f;
    for (int s = tid; s < SS; s += 512) {
        int idx = b * SS + s;
        float v = g_pscore[idx] + g_pscore[BB * SS + idx] +
                  g_pscore[2 * BB * SS + idx] + g_pscore[3 * BB * SS + idx];
        if (mask[idx] == 0) v = -3.402823466e38f;
        sc[s] = v;
        lmax = fmaxf(lmax, v);
    }
    redbuf[tid] = lmax;
    __syncthreads();
    for (int o = 256; o > 0; o >>= 1) {
        if (tid < o) redbuf[tid] = fmaxf(redbuf[tid], redbuf[tid + o]);
        __syncthreads();
    }
    float m = redbuf[0];
    __syncthreads();

    float lsum = 0.f;
    for (int s = tid; s < SS; s += 512) {
        float e = expf(sc[s] - m);
        sc[s] = e;
        lsum += e;
    }
    redbuf[tid] = lsum;
    __syncthreads();
    for (int o = 256; o > 0; o >>= 1) {
        if (tid < o) redbuf[tid] += redbuf[tid + o];
        __syncthreads();
    }
    float inv = 1.f / redbuf[0];
    for (int s = tid; s < SS; s += 512) wout[b * SS + s] = sc[s] * inv;
}

// ---------------------------------------------------------------------------
// context partials from fp16 enc: grid (16, 64), 64 rows/slice, 128 threads.
// Four independent row streams per thread (r, +16, +32, +48) -> 4x MLP.
// ---------------------------------------------------------------------------
__global__ void __launch_bounds__(128) context_part_kernel(
    const float* __restrict__ w) {
    __shared__ float ws[64];
    int sy = blockIdx.x, b = blockIdx.y;
    int e0 = threadIdx.x * 8;
    if (threadIdx.x < 64) ws[threadIdx.x] = w[b * SS + sy * 64 + threadIdx.x];
    __syncthreads();
    const __half* base = g_ench + ((size_t)b * SS + sy * 64) * EE + e0;
    float acc0[8], acc1[8], acc2[8], acc3[8];
#pragma unroll
    for (int j = 0; j < 8; j++) { acc0[j] = 0.f; acc1[j] = 0.f; acc2[j] = 0.f; acc3[j] = 0.f; }
#pragma unroll 4
    for (int r = 0; r < 16; r++) {
        uint4 v0 = *(const uint4*)(base + (size_t)r * EE);
        uint4 v1 = *(const uint4*)(base + (size_t)(r + 16) * EE);
        uint4 v2 = *(const uint4*)(base + (size_t)(r + 32) * EE);
        uint4 v3 = *(const uint4*)(base + (size_t)(r + 48) * EE);
        float c0 = ws[r], c1 = ws[r + 16], c2 = ws[r + 32], c3 = ws[r + 48];
        const uint32_t* p0 = (const uint32_t*)&v0;
        const uint32_t* p1 = (const uint32_t*)&v1;
        const uint32_t* p2 = (const uint32_t*)&v2;
        const uint32_t* p3 = (const uint32_t*)&v3;
#pragma unroll
        for (int q = 0; q < 4; q++) {
            float2 f0 = __half22float2(*(const __half2*)&p0[q]);
            float2 f1 = __half22float2(*(const __half2*)&p1[q]);
            float2 f2 = __half22float2(*(const __half2*)&p2[q]);
            float2 f3 = __half22float2(*(const __half2*)&p3[q]);
            acc0[q * 2 + 0] = fmaf(c0, f0.x, acc0[q * 2 + 0]);
            acc0[q * 2 + 1] = fmaf(c0, f0.y, acc0[q * 2 + 1]);
            acc1[q * 2 + 0] = fmaf(c1, f1.x, acc1[q * 2 + 0]);
            acc1[q * 2 + 1] = fmaf(c1, f1.y, acc1[q * 2 + 1]);
            acc2[q * 2 + 0] = fmaf(c2, f2.x, acc2[q * 2 + 0]);
            acc2[q * 2 + 1] = fmaf(c2, f2.y, acc2[q * 2 + 1]);
            acc3[q * 2 + 0] = fmaf(c3, f3.x, acc3[q * 2 + 0]);
            acc3[q * 2 + 1] = fmaf(c3, f3.y, acc3[q * 2 + 1]);
        }
    }
    float* dst = &g_ctx_part[((size_t)sy * BB + b) * EE + e0];
    *(float4*)dst = make_float4(acc0[0] + acc1[0] + acc2[0] + acc3[0],
                                acc0[1] + acc1[1] + acc2[1] + acc3[1],
                                acc0[2] + acc1[2] + acc2[2] + acc3[2],
                                acc0[3] + acc1[3] + acc2[3] + acc3[3]);
    *(float4*)(dst + 4) = make_float4(acc0[4] + acc1[4] + acc2[4] + acc3[4],
                                      acc0[5] + acc1[5] + acc2[5] + acc3[5],
                                      acc0[6] + acc1[6] + acc2[6] + acc3[6],
                                      acc0[7] + acc1[7] + acc2[7] + acc3[7]);
}

__global__ void context_reduce_kernel(float* __restrict__ ctx) {
    int b = blockIdx.y;
    int e = blockIdx.x * 256 + threadIdx.x;
    float s = 0.f;
#pragma unroll
    for (int sy = 0; sy < 16; sy++) s += g_ctx_part[((size_t)sy * BB + b) * EE + e];
    ctx[b * EE + e] = s;
}

// ---------------------------------------------------------------------------
// host: tensormap encode via driver entry point
// ---------------------------------------------------------------------------
typedef CUresult (*EncodeTiledFn)(
    CUtensorMap*, CUtensorMapDataType, cuuint32_t, void*,
    const cuuint64_t*, const cuuint64_t*, const cuuint32_t*, const cuuint32_t*,
    CUtensorMapInterleave, CUtensorMapSwizzle, CUtensorMapL2promotion,
    CUtensorMapFloatOOBfill);

static EncodeTiledFn get_encode_fn() {
    static EncodeTiledFn fn = nullptr;
    if (!fn) {
        void* p = nullptr;
        cudaDriverEntryPointQueryResult st;
#if CUDART_VERSION >= 12050
        cudaGetDriverEntryPointByVersion("cuTensorMapEncodeTiled", &p, 12000,
                                         cudaEnableDefault, &st);
#else
        cudaGetDriverEntryPoint("cuTensorMapEncodeTiled", &p, cudaEnableDefault, &st);
#endif
        fn = (EncodeTiledFn)p;
    }
    return fn;
}

static void make_tmap_f16(CUtensorMap* tm, void* ptr, uint64_t inner,
                          uint64_t outer, uint32_t box_inner, uint32_t box_outer) {
    cuuint64_t dims[2] = {inner, outer};
    cuuint64_t strides[1] = {inner * 2};
    cuuint32_t box[2] = {box_inner, box_outer};
    cuuint32_t es[2] = {1, 1};
    get_encode_fn()(tm, CU_TENSOR_MAP_DATA_TYPE_FLOAT16, 2, ptr, dims, strides,
                    box, es, CU_TENSOR_MAP_INTERLEAVE_NONE,
                    CU_TENSOR_MAP_SWIZZLE_64B, CU_TENSOR_MAP_L2_PROMOTION_L2_128B,
                    CU_TENSOR_MAP_FLOAT_OOB_FILL_NONE);
}

extern "C" void kernel_launch(void* const* d_in, const int* in_sizes, int n_in,
                              void* d_out, int out_size) {
    const float* hidden = (const float*)d_in[0];   // [B, D]
    const float* enc    = (const float*)d_in[1];   // [B, S, E2]
    const int*   mask   = (const int*)d_in[2];     // [B, S]
    const float* attn_W = (const float*)d_in[3];   // [E2+D, D]
    const float* attn_b = (const float*)d_in[4];   // [D]
    const float* v_W    = (const float*)d_in[5];   // [D]

    float* out = (float*)d_out;
    float* ctx = out;            // context [B, E2]
    float* wts = out + BB * EE;  // attn_weights [B, S]

    cudaFuncSetAttribute(scores_mma_kernel,
                         cudaFuncAttributeMaxDynamicSharedMemorySize, SMEM_SIZE);

    void* ench_ptr = nullptr; cudaGetSymbolAddress(&ench_ptr, g_ench);
    void* weth_ptr = nullptr; cudaGetSymbolAddress(&weth_ptr, g_WeTh);

    CUtensorMap tmA, tmB;
    make_tmap_f16(&tmA, ench_ptr, EE, (uint64_t)BB * SS, BK, BM);  // enc fp16 rows
    make_tmap_f16(&tmB, weth_ptr, EE, DD, BK, BN);                 // WeT fp16 rows

    prep_kernel<<<PREP_BLOCKS, 256>>>(enc, attn_W, attn_b, hidden);
    scores_mma_kernel<<<dim3(4, (BB * SS) / BM), 256, SMEM_SIZE>>>(tmA, tmB, v_W);
    softmax_kernel<<<BB, 512>>>(mask, wts);
    context_part_kernel<<<dim3(16, BB), 128>>>(wts);
    context_reduce_kernel<<<dim3(4, BB), 256>>>(ctx);
}

// round 16
// speedup vs baseline: 1.0087x; 1.0087x over previous
#include <cuda_runtime.h>
#include <cuda.h>
#include <cuda_fp16.h>
#include <math.h>
#include <stdint.h>

#define BB 64
#define SS 1024
#define EE 1024
#define DD 512

// ---------------- device scratch ----------------
__device__ float  g_hp[BB * DD];            // h_proj + bias  [B, D]
__device__ __half g_ench[(size_t)BB * SS * EE];  // enc in fp16 (134 MB)
__device__ __half g_WeTh[DD * EE];          // W_e^T in fp16 [D(n), E2(k)]
__device__ float  g_pscore[4 * BB * SS];    // per-n-tile score partials

// ---------------- helpers ----------------
__device__ __forceinline__ uint32_t smem_u32(const void* p) {
    uint32_t a;
    asm("{ .reg .u64 t; cvta.to.shared.u64 t, %1; cvt.u32.u64 %0, t; }" : "=r"(a) : "l"(p));
    return a;
}

#define MBARRIER_INIT(addr, cnt) \
    asm volatile("mbarrier.init.shared.b64 [%0], %1;" :: "r"(addr), "r"(cnt) : "memory")
#define MBARRIER_INVAL(addr) \
    asm volatile("mbarrier.inval.shared.b64 [%0];" :: "r"(addr) : "memory")
#define MBARRIER_EXPECT_TX(addr, bytes) \
    asm volatile("mbarrier.arrive.expect_tx.shared.b64 _, [%0], %1;" :: "r"(addr), "r"(bytes) : "memory")
#define MBARRIER_WAIT_PARITY(addr, parity) do {                                     \
    uint32_t _m = (addr), _p = (parity);                                            \
    asm volatile(                                                                   \
        "{\n\t.reg .pred P1;\n\t"                                                   \
        "WL_%=:\n\t"                                                                \
        "mbarrier.try_wait.parity.acquire.cta.shared::cta.b64 P1, [%0], %1, 0x989680;\n\t" \
        "@P1 bra.uni WD_%=;\n\t"                                                    \
        "bra.uni WL_%=;\n\t"                                                        \
        "WD_%=:\n\t}"                                                               \
        :: "r"(_m), "r"(_p) : "memory");                                            \
} while (0)
#define TMA_LOAD_2D(smem, map, cx, cy, mbar)                                        \
    asm volatile(                                                                   \
        "cp.async.bulk.tensor.2d.shared::cta.global.tile.mbarrier::complete_tx::bytes " \
        "[%0], [%1, {%2, %3}], [%4];"                                               \
        :: "r"(smem), "l"(map), "r"(cx), "r"(cy), "r"(mbar) : "memory")

__device__ __forceinline__ uint32_t pack_half2(float lo, float hi) {
    uint32_t r;
    asm("cvt.rn.f16x2.f32 %0, %1, %2;" : "=r"(r) : "f"(hi), "f"(lo));
    return r;
}

__device__ __forceinline__ void mma_f16(float c[4], uint32_t a0, uint32_t a1,
                                        uint32_t a2, uint32_t a3, uint32_t b0,
                                        uint32_t b1) {
    asm volatile(
        "mma.sync.aligned.m16n8k16.row.col.f32.f16.f16.f32 "
        "{%0,%1,%2,%3}, {%4,%5,%6,%7}, {%8,%9}, {%0,%1,%2,%3};"
        : "+f"(c[0]), "+f"(c[1]), "+f"(c[2]), "+f"(c[3])
        : "r"(a0), "r"(a1), "r"(a2), "r"(a3), "r"(b0), "r"(b1));
}

// ---------------- tiling ----------------
#define BM 128
#define BN 128
#define BK 32
#define NCHUNK (EE / BK)        // 32
#define A_SZB (BM * 64)         // 8192 (64B rows, TMA SW64)
#define B_SZB (BN * 64)         // 8192
#define STAGE_B (A_SZB + B_SZB) // 16384
#define OFF_SLOT 1024
#define OFF_SHP (OFF_SLOT + 4 * STAGE_B)      // 66560
#define OFF_SV  (OFF_SHP + BN * 4)
#define OFF_RED OFF_SLOT                      // red[128][17] aliases slot 0 (dead)
#define SMEM_SIZE (OFF_SV + BN * 4)           // 67584 B -> 2 CTAs/SM

// ---------------------------------------------------------------------------
// fused prep: convert enc->fp16 (8 elems/thread — R14 proven) | transpose W_e
// | hproj. 256 thr.
// ---------------------------------------------------------------------------
#define CONV_BLOCKS ((BB * SS * EE) / (256 * 8))   // 16384
#define TRANS_BLOCKS ((EE / 32) * (DD / 32))       // 512
#define HPROJ_BLOCKS ((DD / 256) * BB)             // 128
#define PREP_BLOCKS (CONV_BLOCKS + TRANS_BLOCKS + HPROJ_BLOCKS)

__global__ void __launch_bounds__(256) prep_kernel(
    const float* __restrict__ enc, const float* __restrict__ attn_W,
    const float* __restrict__ attn_b, const float* __restrict__ hidden) {
    __shared__ float sbuf[32 * 33 > 512 ? 32 * 33 : 512];
    int bx = blockIdx.x;
    int tid = threadIdx.x;
    if (bx < CONV_BLOCKS) {
        size_t base = ((size_t)bx * 256 + tid) * 8;
        float4 v0 = __ldcs((const float4*)(enc + base));      // f32 enc never re-read
        float4 v1 = __ldcs((const float4*)(enc + base + 4));
        uint4 o;
        o.x = pack_half2(v0.x, v0.y);
        o.y = pack_half2(v0.z, v0.w);
        o.z = pack_half2(v1.x, v1.y);
        o.w = pack_half2(v1.z, v1.w);
        __stcs((uint4*)(&g_ench[base]), o);                   // streaming store
    } else if (bx < CONV_BLOCKS + TRANS_BLOCKS) {
        int id = bx - CONV_BLOCKS;
        int k0 = (id & 31) * 32, d0 = (id >> 5) * 32;
        int x = tid & 31, y = tid >> 5;
        float (*t)[33] = (float(*)[33])sbuf;
        for (int i = y; i < 32; i += 8)
            t[i][x] = attn_W[(size_t)(DD + k0 + i) * DD + d0 + x];
        __syncthreads();
        for (int i = y; i < 32; i += 8)
            g_WeTh[(size_t)(d0 + i) * EE + k0 + x] = __float2half_rn(t[x][i]);
    } else {
        int id = bx - CONV_BLOCKS - TRANS_BLOCKS;
        int b = id >> 1;
        int d = (id & 1) * 256 + tid;
        for (int i = tid; i < DD; i += 256) sbuf[i] = hidden[b * DD + i];
        __syncthreads();
        float acc = attn_b[d];
#pragma unroll 8
        for (int k = 0; k < DD; k++) acc += sbuf[k] * attn_W[k * DD + d];
        g_hp[b * DD + d] = acc;
    }
}

// ---------------------------------------------------------------------------
// scores: fp16 m16n8k16 GEMM (128x128 tile, K=1024), TMA-fed 4-slot pipeline,
// 2 CTAs/SM (launch_bounds(256,2)) -> 4 warps/SMSP.  [unchanged — proven]
// ---------------------------------------------------------------------------
__global__ void __launch_bounds__(256, 2)
scores_mma_kernel(const __grid_constant__ CUtensorMap tmA,
                  const __grid_constant__ CUtensorMap tmB,
                  const float* __restrict__ vW) {
    extern __shared__ char smem[];
    uint32_t sb = smem_u32(smem);
    int tid = threadIdx.x;
    int wid = tid >> 5, lid = tid & 31;
    int gid = lid >> 2, tig = lid & 3;
    int wm = wid >> 2, wn = wid & 3;       // warp grid 2(m) x 4(n)
    int nt = blockIdx.x;                   // n tile (0..3)
    int r0 = blockIdx.y * BM;              // global row
    int b = r0 / SS;
    int n0 = nt * BN;
    int swt = (tig ^ ((gid >> 1) & 3)) * 16;   // loop-invariant swizzled 16B offset

    float* shp = (float*)(smem + OFF_SHP);
    float* sv  = (float*)(smem + OFF_SV);
    for (int i = tid; i < BN; i += 256) {
        shp[i] = g_hp[b * DD + n0 + i];
        sv[i]  = vW[n0 + i];
    }
    if (tid == 0) {
#pragma unroll
        for (int p = 0; p < 4; p++) MBARRIER_INIT(sb + 16 + p * 8, 1);
    }
    __syncthreads();

    if (tid == 0) {
#pragma unroll
        for (int p = 0; p < 4; p++) {
            uint32_t slot = sb + OFF_SLOT + p * STAGE_B;
            MBARRIER_EXPECT_TX(sb + 16 + p * 8, (uint32_t)STAGE_B);
            TMA_LOAD_2D(slot, &tmA, p * BK, r0, sb + 16 + p * 8);
            TMA_LOAD_2D(slot + A_SZB, &tmB, p * BK, n0, sb + 16 + p * 8);
        }
    }

    float acc[4][4][4];
#pragma unroll
    for (int mf = 0; mf < 4; mf++)
#pragma unroll
        for (int nf = 0; nf < 4; nf++)
#pragma unroll
            for (int q = 0; q < 4; q++) acc[mf][nf][q] = 0.f;

#pragma unroll 4
    for (int c = 0; c < NCHUNK; c++) {
        int slot = c & 3;
        uint32_t mb = sb + 16 + slot * 8;
        MBARRIER_WAIT_PARITY(mb, (uint32_t)((c >> 2) & 1));

        const char* fA = smem + OFF_SLOT + slot * STAGE_B;
        const char* fB = fA + A_SZB;

        uint4 alo[4], ahi[4], bv[4];   // 8 halves each: phys k = 8*tig..+7
#pragma unroll
        for (int mf = 0; mf < 4; mf++) {
            int m0 = wm * 64 + mf * 16 + gid;
            alo[mf] = *(const uint4*)(fA + m0 * 64 + swt);
            ahi[mf] = *(const uint4*)(fA + (m0 + 8) * 64 + swt);
        }
#pragma unroll
        for (int nf = 0; nf < 4; nf++) {
            int nr = wn * 32 + nf * 8 + gid;
            bv[nf] = *(const uint4*)(fB + nr * 64 + swt);
        }
        __syncthreads();   // all warps consumed this slot
        if (c + 4 < NCHUNK && tid == 0) {
            uint32_t sdst = sb + OFF_SLOT + slot * STAGE_B;
            MBARRIER_EXPECT_TX(mb, (uint32_t)STAGE_B);
            TMA_LOAD_2D(sdst, &tmA, (c + 4) * BK, r0, mb);
            TMA_LOAD_2D(sdst + A_SZB, &tmB, (c + 4) * BK, n0, mb);
        }

        // instr 0: half-pairs 0,1 (phys k 8t..8t+3)
#pragma unroll
        for (int mf = 0; mf < 4; mf++)
#pragma unroll
            for (int nf = 0; nf < 4; nf++)
                mma_f16(acc[mf][nf], alo[mf].x, ahi[mf].x, alo[mf].y, ahi[mf].y,
                        bv[nf].x, bv[nf].y);
        // instr 1: half-pairs 2,3 (phys k 8t+4..8t+7)
#pragma unroll
        for (int mf = 0; mf < 4; mf++)
#pragma unroll
            for (int nf = 0; nf < 4; nf++)
                mma_f16(acc[mf][nf], alo[mf].z, ahi[mf].z, alo[mf].w, ahi[mf].w,
                        bv[nf].z, bv[nf].w);
    }
    __syncthreads();   // slots dead; red aliases slot 0

    // ---- epilogue: score partial = sum_n v[n] * tanh(acc + hp[n]) ----
    float* red = (float*)(smem + OFF_RED);  // [128][17]
#pragma unroll
    for (int mf = 0; mf < 4; mf++) {
#pragma unroll
        for (int half = 0; half < 2; half++) {
            int r = wm * 64 + mf * 16 + half * 8 + gid;
            float s = 0.f;
#pragma unroll
            for (int nf = 0; nf < 4; nf++) {
                int nl = wn * 32 + nf * 8 + tig * 2;
                float e0 = acc[mf][nf][half * 2 + 0] + shp[nl];
                float e1 = acc[mf][nf][half * 2 + 1] + shp[nl + 1];
                float t0, t1;
                asm("tanh.approx.f32 %0, %1;" : "=f"(t0) : "f"(e0));
                asm("tanh.approx.f32 %0, %1;" : "=f"(t1) : "f"(e1));
                s = fmaf(sv[nl], t0, s);
                s = fmaf(sv[nl + 1], t1, s);
            }
            red[r * 17 + wn * 4 + tig] = s;
        }
    }
    __syncthreads();
    if (tid < BM) {
        float s = 0.f;
#pragma unroll
        for (int t = 0; t < 16; t++) s += red[tid * 17 + t];
        g_pscore[nt * (BB * SS) + r0 + tid] = s;
    }
    __syncthreads();
    if (tid == 0) {
#pragma unroll
        for (int p = 0; p < 4; p++) MBARRIER_INVAL(sb + 16 + p * 8);
    }
}

// ---------------------------------------------------------------------------
// softmax: combine 4 partials, mask, softmax over S. Also zeroes ctx[b,:]
// so context_part can atomically accumulate into it. grid(64), 512 threads.
// ---------------------------------------------------------------------------
__global__ void softmax_kernel(const int* __restrict__ mask,
                               float* __restrict__ wout,
                               float* __restrict__ ctx) {
    int b = blockIdx.x;
    __shared__ float sc[SS];
    __shared__ float redbuf[512];
    int tid = threadIdx.x;

    // zero the context row for this batch (EE floats)
    for (int e = tid; e < EE; e += 512) ctx[b * EE + e] = 0.f;

    float lmax = -3.402823466e38f;
    for (int s = tid; s < SS; s += 512) {
        int idx = b * SS + s;
        float v = g_pscore[idx] + g_pscore[BB * SS + idx] +
                  g_pscore[2 * BB * SS + idx] + g_pscore[3 * BB * SS + idx];
        if (mask[idx] == 0) v = -3.402823466e38f;
        sc[s] = v;
        lmax = fmaxf(lmax, v);
    }
    redbuf[tid] = lmax;
    __syncthreads();
    for (int o = 256; o > 0; o >>= 1) {
        if (tid < o) redbuf[tid] = fmaxf(redbuf[tid], redbuf[tid + o]);
        __syncthreads();
    }
    float m = redbuf[0];
    __syncthreads();

    float lsum = 0.f;
    for (int s = tid; s < SS; s += 512) {
        float e = expf(sc[s] - m);
        sc[s] = e;
        lsum += e;
    }
    redbuf[tid] = lsum;
    __syncthreads();
    for (int o = 256; o > 0; o >>= 1) {
        if (tid < o) redbuf[tid] += redbuf[tid + o];
        __syncthreads();
    }
    float inv = 1.f / redbuf[0];
    for (int s = tid; s < SS; s += 512) wout[b * SS + s] = sc[s] * inv;
}

// ---------------------------------------------------------------------------
// context partials from fp16 enc: grid (16, 64), 64 rows/slice, 128 threads.
// Two independent row streams per thread (R14 proven). Accumulates directly
// into ctx via atomicAdd (softmax zeroed it; stream order guarantees).
// ---------------------------------------------------------------------------
__global__ void __launch_bounds__(128) context_part_kernel(
    const float* __restrict__ w, float* __restrict__ ctx) {
    __shared__ float ws[64];
    int sy = blockIdx.x, b = blockIdx.y;
    int e0 = threadIdx.x * 8;
    if (threadIdx.x < 64) ws[threadIdx.x] = w[b * SS + sy * 64 + threadIdx.x];
    __syncthreads();
    const __half* base0 = g_ench + ((size_t)b * SS + sy * 64) * EE + e0;
    const __half* base1 = base0 + (size_t)32 * EE;
    float acc0[8], acc1[8];
#pragma unroll
    for (int j = 0; j < 8; j++) { acc0[j] = 0.f; acc1[j] = 0.f; }
#pragma unroll 4
    for (int r = 0; r < 32; r++) {
        uint4 v0 = *(const uint4*)(base0 + (size_t)r * EE);
        uint4 v1 = *(const uint4*)(base1 + (size_t)r * EE);
        float c0 = ws[r], c1 = ws[r + 32];
        const uint32_t* p0 = (const uint32_t*)&v0;
        const uint32_t* p1 = (const uint32_t*)&v1;
#pragma unroll
        for (int q = 0; q < 4; q++) {
            float2 f0 = __half22float2(*(const __half2*)&p0[q]);
            float2 f1 = __half22float2(*(const __half2*)&p1[q]);
            acc0[q * 2 + 0] = fmaf(c0, f0.x, acc0[q * 2 + 0]);
            acc0[q * 2 + 1] = fmaf(c0, f0.y, acc0[q * 2 + 1]);
            acc1[q * 2 + 0] = fmaf(c1, f1.x, acc1[q * 2 + 0]);
            acc1[q * 2 + 1] = fmaf(c1, f1.y, acc1[q * 2 + 1]);
        }
    }
    float* dst = &ctx[(size_t)b * EE + e0];
#pragma unroll
    for (int j = 0; j < 8; j++) atomicAdd(dst + j, acc0[j] + acc1[j]);
}

// ---------------------------------------------------------------------------
// host: tensormap encode via driver entry point
// ---------------------------------------------------------------------------
typedef CUresult (*EncodeTiledFn)(
    CUtensorMap*, CUtensorMapDataType, cuuint32_t, void*,
    const cuuint64_t*, const cuuint64_t*, const cuuint32_t*, const cuuint32_t*,
    CUtensorMapInterleave, CUtensorMapSwizzle, CUtensorMapL2promotion,
    CUtensorMapFloatOOBfill);

static EncodeTiledFn get_encode_fn() {
    static EncodeTiledFn fn = nullptr;
    if (!fn) {
        void* p = nullptr;
        cudaDriverEntryPointQueryResult st;
#if CUDART_VERSION >= 12050
        cudaGetDriverEntryPointByVersion("cuTensorMapEncodeTiled", &p, 12000,
                                         cudaEnableDefault, &st);
#else
        cudaGetDriverEntryPoint("cuTensorMapEncodeTiled", &p, cudaEnableDefault, &st);
#endif
        fn = (EncodeTiledFn)p;
    }
    return fn;
}

static void make_tmap_f16(CUtensorMap* tm, void* ptr, uint64_t inner,
                          uint64_t outer, uint32_t box_inner, uint32_t box_outer) {
    cuuint64_t dims[2] = {inner, outer};
    cuuint64_t strides[1] = {inner * 2};
    cuuint32_t box[2] = {box_inner, box_outer};
    cuuint32_t es[2] = {1, 1};
    get_encode_fn()(tm, CU_TENSOR_MAP_DATA_TYPE_FLOAT16, 2, ptr, dims, strides,
                    box, es, CU_TENSOR_MAP_INTERLEAVE_NONE,
                    CU_TENSOR_MAP_SWIZZLE_64B, CU_TENSOR_MAP_L2_PROMOTION_L2_128B,
                    CU_TENSOR_MAP_FLOAT_OOB_FILL_NONE);
}

extern "C" void kernel_launch(void* const* d_in, const int* in_sizes, int n_in,
                              void* d_out, int out_size) {
    const float* hidden = (const float*)d_in[0];   // [B, D]
    const float* enc    = (const float*)d_in[1];   // [B, S, E2]
    const int*   mask   = (const int*)d_in[2];     // [B, S]
    const float* attn_W = (const float*)d_in[3];   // [E2+D, D]
    const float* attn_b = (const float*)d_in[4];   // [D]
    const float* v_W    = (const float*)d_in[5];   // [D]

    float* out = (float*)d_out;
    float* ctx = out;            // context [B, E2]
    float* wts = out + BB * EE;  // attn_weights [B, S]

    cudaFuncSetAttribute(scores_mma_kernel,
                         cudaFuncAttributeMaxDynamicSharedMemorySize, SMEM_SIZE);

    void* ench_ptr = nullptr; cudaGetSymbolAddress(&ench_ptr, g_ench);
    void* weth_ptr = nullptr; cudaGetSymbolAddress(&weth_ptr, g_WeTh);

    CUtensorMap tmA, tmB;
    make_tmap_f16(&tmA, ench_ptr, EE, (uint64_t)BB * SS, BK, BM);  // enc fp16 rows
    make_tmap_f16(&tmB, weth_ptr, EE, DD, BK, BN);                 // WeT fp16 rows

    prep_kernel<<<PREP_BLOCKS, 256>>>(enc, attn_W, attn_b, hidden);
    scores_mma_kernel<<<dim3(4, (BB * SS) / BM), 256, SMEM_SIZE>>>(tmA, tmB, v_W);
    softmax_kernel<<<BB, 512>>>(mask, wts, ctx);
    context_part_kernel<<<dim3(16, BB), 128>>>(wts, ctx);
}

// round 17
// speedup vs baseline: 1.0290x; 1.0201x over previous
#include <cuda_runtime.h>
#include <cuda.h>
#include <cuda_fp16.h>
#include <math.h>
#include <stdint.h>

#define BB 64
#define SS 1024
#define EE 1024
#define DD 512

// ---------------- device scratch ----------------
__device__ float  g_hp[BB * DD];            // h_proj + bias  [B, D]
__device__ __half g_ench[(size_t)BB * SS * EE];  // enc in fp16 (134 MB)
__device__ __half g_WeTh[DD * EE];          // W_e^T in fp16 [D(n), E2(k)]
__device__ float  g_pscore[4 * BB * SS];    // per-n-tile score partials
__device__ float  g_ctx_part[16 * BB * EE]; // context partials (16 S-slices)

// ---------------- helpers ----------------
__device__ __forceinline__ uint32_t smem_u32(const void* p) {
    uint32_t a;
    asm("{ .reg .u64 t; cvta.to.shared.u64 t, %1; cvt.u32.u64 %0, t; }" : "=r"(a) : "l"(p));
    return a;
}

#define MBARRIER_INIT(addr, cnt) \
    asm volatile("mbarrier.init.shared.b64 [%0], %1;" :: "r"(addr), "r"(cnt) : "memory")
#define MBARRIER_INVAL(addr) \
    asm volatile("mbarrier.inval.shared.b64 [%0];" :: "r"(addr) : "memory")
#define MBARRIER_EXPECT_TX(addr, bytes) \
    asm volatile("mbarrier.arrive.expect_tx.shared.b64 _, [%0], %1;" :: "r"(addr), "r"(bytes) : "memory")
#define MBARRIER_WAIT_PARITY(addr, parity) do {                                     \
    uint32_t _m = (addr), _p = (parity);                                            \
    asm volatile(                                                                   \
        "{\n\t.reg .pred P1;\n\t"                                                   \
        "WL_%=:\n\t"                                                                \
        "mbarrier.try_wait.parity.acquire.cta.shared::cta.b64 P1, [%0], %1, 0x989680;\n\t" \
        "@P1 bra.uni WD_%=;\n\t"                                                    \
        "bra.uni WL_%=;\n\t"                                                        \
        "WD_%=:\n\t}"                                                               \
        :: "r"(_m), "r"(_p) : "memory");                                            \
} while (0)
#define TMA_LOAD_2D(smem, map, cx, cy, mbar)                                        \
    asm volatile(                                                                   \
        "cp.async.bulk.tensor.2d.shared::cta.global.tile.mbarrier::complete_tx::bytes " \
        "[%0], [%1, {%2, %3}], [%4];"                                               \
        :: "r"(smem), "l"(map), "r"(cx), "r"(cy), "r"(mbar) : "memory")

__device__ __forceinline__ uint32_t pack_half2(float lo, float hi) {
    uint32_t r;
    asm("cvt.rn.f16x2.f32 %0, %1, %2;" : "=r"(r) : "f"(hi), "f"(lo));
    return r;
}

__device__ __forceinline__ void mma_f16(float c[4], uint32_t a0, uint32_t a1,
                                        uint32_t a2, uint32_t a3, uint32_t b0,
                                        uint32_t b1) {
    asm volatile(
        "mma.sync.aligned.m16n8k16.row.col.f32.f16.f16.f32 "
        "{%0,%1,%2,%3}, {%4,%5,%6,%7}, {%8,%9}, {%0,%1,%2,%3};"
        : "+f"(c[0]), "+f"(c[1]), "+f"(c[2]), "+f"(c[3])
        : "r"(a0), "r"(a1), "r"(a2), "r"(a3), "r"(b0), "r"(b1));
}

// ---------------- tiling ----------------
#define BM 128
#define BN 128
#define BK 32
#define NCHUNK (EE / BK)        // 32
#define A_SZB (BM * 64)         // 8192 (64B rows, TMA SW64)
#define B_SZB (BN * 64)         // 8192
#define STAGE_B (A_SZB + B_SZB) // 16384
#define OFF_SLOT 1024
#define OFF_SHP (OFF_SLOT + 4 * STAGE_B)      // 66560
#define OFF_SV  (OFF_SHP + BN * 4)
#define OFF_RED OFF_SLOT                      // red[128][17] aliases slot 0 (dead)
#define SMEM_SIZE (OFF_SV + BN * 4)           // 67584 B -> 2 CTAs/SM

// ---------------------------------------------------------------------------
// conv device helper: convert 2048 f32 elements per block (8/thread)
// ---------------------------------------------------------------------------
__device__ __forceinline__ void conv_block(const float* __restrict__ enc,
                                           size_t elem_base) {
    float4 v0 = __ldcs((const float4*)(enc + elem_base));
    float4 v1 = __ldcs((const float4*)(enc + elem_base + 4));
    uint4 o;
    o.x = pack_half2(v0.x, v0.y);
    o.y = pack_half2(v0.z, v0.w);
    o.z = pack_half2(v1.x, v1.y);
    o.w = pack_half2(v1.z, v1.w);
    __stcs((uint4*)(&g_ench[elem_base]), o);
}

#define HALF_ELEMS ((size_t)BB * SS * EE / 2)      // 33,554,432
#define CONV_HALF_BLOCKS (HALF_ELEMS / (256 * 8))  // 16384/2 = 8192
#define TRANS_BLOCKS ((EE / 32) * (DD / 32))       // 512
#define HPROJ_BLOCKS ((DD / 256) * BB)             // 128
#define PREP0_BLOCKS (CONV_HALF_BLOCKS + TRANS_BLOCKS + HPROJ_BLOCKS)

// prep0: conv of FIRST half of enc + transpose W_e + hproj
__global__ void __launch_bounds__(256) prep0_kernel(
    const float* __restrict__ enc, const float* __restrict__ attn_W,
    const float* __restrict__ attn_b, const float* __restrict__ hidden) {
    __shared__ float sbuf[32 * 33 > 512 ? 32 * 33 : 512];
    int bx = blockIdx.x;
    int tid = threadIdx.x;
    if (bx < CONV_HALF_BLOCKS) {
        conv_block(enc, ((size_t)bx * 256 + tid) * 8);
    } else if (bx < CONV_HALF_BLOCKS + TRANS_BLOCKS) {
        int id = bx - CONV_HALF_BLOCKS;
        int k0 = (id & 31) * 32, d0 = (id >> 5) * 32;
        int x = tid & 31, y = tid >> 5;
        float (*t)[33] = (float(*)[33])sbuf;
        for (int i = y; i < 32; i += 8)
            t[i][x] = attn_W[(size_t)(DD + k0 + i) * DD + d0 + x];
        __syncthreads();
        for (int i = y; i < 32; i += 8)
            g_WeTh[(size_t)(d0 + i) * EE + k0 + x] = __float2half_rn(t[x][i]);
    } else {
        int id = bx - CONV_HALF_BLOCKS - TRANS_BLOCKS;
        int b = id >> 1;
        int d = (id & 1) * 256 + tid;
        for (int i = tid; i < DD; i += 256) sbuf[i] = hidden[b * DD + i];
        __syncthreads();
        float acc = attn_b[d];
#pragma unroll 8
        for (int k = 0; k < DD; k++) acc += sbuf[k] * attn_W[k * DD + d];
        g_hp[b * DD + d] = acc;
    }
}

// conv1: conv of SECOND half of enc (runs on side stream under scores half0)
__global__ void __launch_bounds__(256) conv1_kernel(const float* __restrict__ enc) {
    conv_block(enc, HALF_ELEMS + ((size_t)blockIdx.x * 256 + threadIdx.x) * 8);
}

// ---------------------------------------------------------------------------
// scores: fp16 m16n8k16 GEMM (128x128 tile, K=1024), TMA-fed 4-slot pipeline,
// 2 CTAs/SM. rbase selects the row half. [mainloop unchanged — proven]
// ---------------------------------------------------------------------------
__global__ void __launch_bounds__(256, 2)
scores_mma_kernel(const __grid_constant__ CUtensorMap tmA,
                  const __grid_constant__ CUtensorMap tmB,
                  const float* __restrict__ vW, int rbase) {
    extern __shared__ char smem[];
    uint32_t sb = smem_u32(smem);
    int tid = threadIdx.x;
    int wid = tid >> 5, lid = tid & 31;
    int gid = lid >> 2, tig = lid & 3;
    int wm = wid >> 2, wn = wid & 3;       // warp grid 2(m) x 4(n)
    int nt = blockIdx.x;                   // n tile (0..3)
    int r0 = rbase + blockIdx.y * BM;      // global row
    int b = r0 / SS;
    int n0 = nt * BN;
    int swt = (tig ^ ((gid >> 1) & 3)) * 16;   // loop-invariant swizzled 16B offset

    float* shp = (float*)(smem + OFF_SHP);
    float* sv  = (float*)(smem + OFF_SV);
    for (int i = tid; i < BN; i += 256) {
        shp[i] = g_hp[b * DD + n0 + i];
        sv[i]  = vW[n0 + i];
    }
    if (tid == 0) {
#pragma unroll
        for (int p = 0; p < 4; p++) MBARRIER_INIT(sb + 16 + p * 8, 1);
    }
    __syncthreads();

    if (tid == 0) {
#pragma unroll
        for (int p = 0; p < 4; p++) {
            uint32_t slot = sb + OFF_SLOT + p * STAGE_B;
            MBARRIER_EXPECT_TX(sb + 16 + p * 8, (uint32_t)STAGE_B);
            TMA_LOAD_2D(slot, &tmA, p * BK, r0, sb + 16 + p * 8);
            TMA_LOAD_2D(slot + A_SZB, &tmB, p * BK, n0, sb + 16 + p * 8);
        }
    }

    float acc[4][4][4];
#pragma unroll
    for (int mf = 0; mf < 4; mf++)
#pragma unroll
        for (int nf = 0; nf < 4; nf++)
#pragma unroll
            for (int q = 0; q < 4; q++) acc[mf][nf][q] = 0.f;

#pragma unroll 4
    for (int c = 0; c < NCHUNK; c++) {
        int slot = c & 3;
        uint32_t mb = sb + 16 + slot * 8;
        MBARRIER_WAIT_PARITY(mb, (uint32_t)((c >> 2) & 1));

        const char* fA = smem + OFF_SLOT + slot * STAGE_B;
        const char* fB = fA + A_SZB;

        uint4 alo[4], ahi[4], bv[4];   // 8 halves each: phys k = 8*tig..+7
#pragma unroll
        for (int mf = 0; mf < 4; mf++) {
            int m0 = wm * 64 + mf * 16 + gid;
            alo[mf] = *(const uint4*)(fA + m0 * 64 + swt);
            ahi[mf] = *(const uint4*)(fA + (m0 + 8) * 64 + swt);
        }
#pragma unroll
        for (int nf = 0; nf < 4; nf++) {
            int nr = wn * 32 + nf * 8 + gid;
            bv[nf] = *(const uint4*)(fB + nr * 64 + swt);
        }
        __syncthreads();   // all warps consumed this slot
        if (c + 4 < NCHUNK && tid == 0) {
            uint32_t sdst = sb + OFF_SLOT + slot * STAGE_B;
            MBARRIER_EXPECT_TX(mb, (uint32_t)STAGE_B);
            TMA_LOAD_2D(sdst, &tmA, (c + 4) * BK, r0, mb);
            TMA_LOAD_2D(sdst + A_SZB, &tmB, (c + 4) * BK, n0, mb);
        }

        // instr 0: half-pairs 0,1 (phys k 8t..8t+3)
#pragma unroll
        for (int mf = 0; mf < 4; mf++)
#pragma unroll
            for (int nf = 0; nf < 4; nf++)
                mma_f16(acc[mf][nf], alo[mf].x, ahi[mf].x, alo[mf].y, ahi[mf].y,
                        bv[nf].x, bv[nf].y);
        // instr 1: half-pairs 2,3 (phys k 8t+4..8t+7)
#pragma unroll
        for (int mf = 0; mf < 4; mf++)
#pragma unroll
            for (int nf = 0; nf < 4; nf++)
                mma_f16(acc[mf][nf], alo[mf].z, ahi[mf].z, alo[mf].w, ahi[mf].w,
                        bv[nf].z, bv[nf].w);
    }
    __syncthreads();   // slots dead; red aliases slot 0

    // ---- epilogue: score partial = sum_n v[n] * tanh(acc + hp[n]) ----
    float* red = (float*)(smem + OFF_RED);  // [128][17]
#pragma unroll
    for (int mf = 0; mf < 4; mf++) {
#pragma unroll
        for (int half = 0; half < 2; half++) {
            int r = wm * 64 + mf * 16 + half * 8 + gid;
            float s = 0.f;
#pragma unroll
            for (int nf = 0; nf < 4; nf++) {
                int nl = wn * 32 + nf * 8 + tig * 2;
                float e0 = acc[mf][nf][half * 2 + 0] + shp[nl];
                float e1 = acc[mf][nf][half * 2 + 1] + shp[nl + 1];
                float t0, t1;
                asm("tanh.approx.f32 %0, %1;" : "=f"(t0) : "f"(e0));
                asm("tanh.approx.f32 %0, %1;" : "=f"(t1) : "f"(e1));
                s = fmaf(sv[nl], t0, s);
                s = fmaf(sv[nl + 1], t1, s);
            }
            red[r * 17 + wn * 4 + tig] = s;
        }
    }
    __syncthreads();
    if (tid < BM) {
        float s = 0.f;
#pragma unroll
        for (int t = 0; t < 16; t++) s += red[tid * 17 + t];
        g_pscore[nt * (BB * SS) + r0 + tid] = s;
    }
    __syncthreads();
    if (tid == 0) {
#pragma unroll
        for (int p = 0; p < 4; p++) MBARRIER_INVAL(sb + 16 + p * 8);
    }
}

// ---------------------------------------------------------------------------
// softmax: combine 4 partials, mask, softmax over S. grid(64), 512 threads.
// ---------------------------------------------------------------------------
__global__ void softmax_kernel(const int* __restrict__ mask,
                               float* __restrict__ wout) {
    int b = blockIdx.x;
    __shared__ float sc[SS];
    __shared__ float redbuf[512];
    int tid = threadIdx.x;

    float lmax = -3.402823466e38f;
    for (int s = tid; s < SS; s += 512) {
        int idx = b * SS + s;
        float v = g_pscore[idx] + g_pscore[BB * SS + idx] +
                  g_pscore[2 * BB * SS + idx] + g_pscore[3 * BB * SS + idx];
        if (mask[idx] == 0) v = -3.402823466e38f;
        sc[s] = v;
        lmax = fmaxf(lmax, v);
    }
    redbuf[tid] = lmax;
    __syncthreads();
    for (int o = 256; o > 0; o >>= 1) {
        if (tid < o) redbuf[tid] = fmaxf(redbuf[tid], redbuf[tid + o]);
        __syncthreads();
    }
    float m = redbuf[0];
    __syncthreads();

    float lsum = 0.f;
    for (int s = tid; s < SS; s += 512) {
        float e = expf(sc[s] - m);
        sc[s] = e;
        lsum += e;
    }
    redbuf[tid] = lsum;
    __syncthreads();
    for (int o = 256; o > 0; o >>= 1) {
        if (tid < o) redbuf[tid] += redbuf[tid + o];
        __syncthreads();
    }
    float inv = 1.f / redbuf[0];
    for (int s = tid; s < SS; s += 512) wout[b * SS + s] = sc[s] * inv;
}

// ---------------------------------------------------------------------------
// context partials from fp16 enc: grid (16, 64), 64 rows/slice, 128 threads.
// Two independent row streams per thread. [R14 proven]
// ---------------------------------------------------------------------------
__global__ void __launch_bounds__(128) context_part_kernel(
    const float* __restrict__ w) {
    __shared__ float ws[64];
    int sy = blockIdx.x, b = blockIdx.y;
    int e0 = threadIdx.x * 8;
    if (threadIdx.x < 64) ws[threadIdx.x] = w[b * SS + sy * 64 + threadIdx.x];
    __syncthreads();
    const __half* base0 = g_ench + ((size_t)b * SS + sy * 64) * EE + e0;
    const __half* base1 = base0 + (size_t)32 * EE;
    float acc0[8], acc1[8];
#pragma unroll
    for (int j = 0; j < 8; j++) { acc0[j] = 0.f; acc1[j] = 0.f; }
#pragma unroll 4
    for (int r = 0; r < 32; r++) {
        uint4 v0 = *(const uint4*)(base0 + (size_t)r * EE);
        uint4 v1 = *(const uint4*)(base1 + (size_t)r * EE);
        float c0 = ws[r], c1 = ws[r + 32];
        const uint32_t* p0 = (const uint32_t*)&v0;
        const uint32_t* p1 = (const uint32_t*)&v1;
#pragma unroll
        for (int q = 0; q < 4; q++) {
            float2 f0 = __half22float2(*(const __half2*)&p0[q]);
            float2 f1 = __half22float2(*(const __half2*)&p1[q]);
            acc0[q * 2 + 0] = fmaf(c0, f0.x, acc0[q * 2 + 0]);
            acc0[q * 2 + 1] = fmaf(c0, f0.y, acc0[q * 2 + 1]);
            acc1[q * 2 + 0] = fmaf(c1, f1.x, acc1[q * 2 + 0]);
            acc1[q * 2 + 1] = fmaf(c1, f1.y, acc1[q * 2 + 1]);
        }
    }
    float* dst = &g_ctx_part[((size_t)sy * BB + b) * EE + e0];
    *(float4*)dst = make_float4(acc0[0] + acc1[0], acc0[1] + acc1[1],
                                acc0[2] + acc1[2], acc0[3] + acc1[3]);
    *(float4*)(dst + 4) = make_float4(acc0[4] + acc1[4], acc0[5] + acc1[5],
                                      acc0[6] + acc1[6], acc0[7] + acc1[7]);
}

__global__ void context_reduce_kernel(float* __restrict__ ctx) {
    int b = blockIdx.y;
    int e = blockIdx.x * 256 + threadIdx.x;
    float s = 0.f;
#pragma unroll
    for (int sy = 0; sy < 16; sy++) s += g_ctx_part[((size_t)sy * BB + b) * EE + e];
    ctx[b * EE + e] = s;
}

// ---------------------------------------------------------------------------
// host: tensormap encode via driver entry point
// ---------------------------------------------------------------------------
typedef CUresult (*EncodeTiledFn)(
    CUtensorMap*, CUtensorMapDataType, cuuint32_t, void*,
    const cuuint64_t*, const cuuint64_t*, const cuuint32_t*, const cuuint32_t*,
    CUtensorMapInterleave, CUtensorMapSwizzle, CUtensorMapL2promotion,
    CUtensorMapFloatOOBfill);

static EncodeTiledFn get_encode_fn() {
    static EncodeTiledFn fn = nullptr;
    if (!fn) {
        void* p = nullptr;
        cudaDriverEntryPointQueryResult st;
#if CUDART_VERSION >= 12050
        cudaGetDriverEntryPointByVersion("cuTensorMapEncodeTiled", &p, 12000,
                                         cudaEnableDefault, &st);
#else
        cudaGetDriverEntryPoint("cuTensorMapEncodeTiled", &p, cudaEnableDefault, &st);
#endif
        fn = (EncodeTiledFn)p;
    }
    return fn;
}

static void make_tmap_f16(CUtensorMap* tm, void* ptr, uint64_t inner,
                          uint64_t outer, uint32_t box_inner, uint32_t box_outer) {
    cuuint64_t dims[2] = {inner, outer};
    cuuint64_t strides[1] = {inner * 2};
    cuuint32_t box[2] = {box_inner, box_outer};
    cuuint32_t es[2] = {1, 1};
    get_encode_fn()(tm, CU_TENSOR_MAP_DATA_TYPE_FLOAT16, 2, ptr, dims, strides,
                    box, es, CU_TENSOR_MAP_INTERLEAVE_NONE,
                    CU_TENSOR_MAP_SWIZZLE_64B, CU_TENSOR_MAP_L2_PROMOTION_L2_128B,
                    CU_TENSOR_MAP_FLOAT_OOB_FILL_NONE);
}

extern "C" void kernel_launch(void* const* d_in, const int* in_sizes, int n_in,
                              void* d_out, int out_size) {
    const float* hidden = (const float*)d_in[0];   // [B, D]
    const float* enc    = (const float*)d_in[1];   // [B, S, E2]
    const int*   mask   = (const int*)d_in[2];     // [B, S]
    const float* attn_W = (const float*)d_in[3];   // [E2+D, D]
    const float* attn_b = (const float*)d_in[4];   // [D]
    const float* v_W    = (const float*)d_in[5];   // [D]

    float* out = (float*)d_out;
    float* ctx = out;            // context [B, E2]
    float* wts = out + BB * EE;  // attn_weights [B, S]

    // One-time resources (created on the non-captured correctness call)
    static bool inited = false;
    static cudaStream_t s1;
    static cudaEvent_t evPrep0, evConv1;
    if (!inited) {
        cudaFuncSetAttribute(scores_mma_kernel,
                             cudaFuncAttributeMaxDynamicSharedMemorySize, SMEM_SIZE);
        cudaStreamCreateWithFlags(&s1, cudaStreamNonBlocking);
        cudaEventCreateWithFlags(&evPrep0, cudaEventDisableTiming);
        cudaEventCreateWithFlags(&evConv1, cudaEventDisableTiming);
        inited = true;
    }

    void* ench_ptr = nullptr; cudaGetSymbolAddress(&ench_ptr, g_ench);
    void* weth_ptr = nullptr; cudaGetSymbolAddress(&weth_ptr, g_WeTh);

    CUtensorMap tmA, tmB;
    make_tmap_f16(&tmA, ench_ptr, EE, (uint64_t)BB * SS, BK, BM);  // enc fp16 rows
    make_tmap_f16(&tmB, weth_ptr, EE, DD, BK, BN);                 // WeT fp16 rows

    const int HALF_TILES = (BB * SS / 2) / BM;   // 256 row tiles per half

    // s0: prep half0 (+weights) -> scores half0
    prep0_kernel<<<PREP0_BLOCKS, 256>>>(enc, attn_W, attn_b, hidden);
    cudaEventRecord(evPrep0, 0);
    scores_mma_kernel<<<dim3(4, HALF_TILES), 256, SMEM_SIZE>>>(tmA, tmB, v_W, 0);

    // s1: conv half1 concurrently with scores half0
    cudaStreamWaitEvent(s1, evPrep0, 0);
    conv1_kernel<<<CONV_HALF_BLOCKS, 256, 0, s1>>>(enc);
    cudaEventRecord(evConv1, s1);

    // s0: scores half1 after conv1
    cudaStreamWaitEvent(0, evConv1, 0);
    scores_mma_kernel<<<dim3(4, HALF_TILES), 256, SMEM_SIZE>>>(tmA, tmB, v_W,
                                                              BB * SS / 2);
    softmax_kernel<<<BB, 512>>>(mask, wts);
    context_part_kernel<<<dim3(16, BB), 128>>>(wts);
    context_reduce_kernel<<<dim3(4, BB), 256>>>(ctx);
}